// round 7
// baseline (speedup 1.0000x reference)
#include <cuda_runtime.h>
#include <cstdint>

#define NN 50000
#define NE 800000
#define NG 256
#define NTILE 6250          // NE / 128
#define PGRID 152

typedef unsigned long long ull;

// ---------------- tf32 mma.sync helpers ----------------
__device__ __forceinline__ uint32_t f2tf(float f) {
    uint32_t r; asm("cvt.rna.tf32.f32 %0, %1;" : "=r"(r) : "f"(f)); return r;
}
__device__ __forceinline__ void mma8(float* d, const uint32_t* a, uint32_t b0, uint32_t b1) {
    asm volatile("mma.sync.aligned.m16n8k8.row.col.f32.tf32.tf32.f32 "
        "{%0,%1,%2,%3},{%4,%5,%6,%7},{%8,%9},{%0,%1,%2,%3};"
        : "+f"(d[0]), "+f"(d[1]), "+f"(d[2]), "+f"(d[3])
        : "r"(a[0]), "r"(a[1]), "r"(a[2]), "r"(a[3]), "r"(b0), "r"(b1));
}

// ---------------- f32x2 helpers ----------------
__device__ __forceinline__ void ffma2(ull &d, ull a, ull b) {
    asm("fma.rn.f32x2 %0, %1, %2, %0;" : "+l"(d) : "l"(a), "l"(b));
}
__device__ __forceinline__ ull pack2(float lo, float hi) {
    ull r; asm("mov.b64 %0, {%1, %2};" : "=l"(r) : "f"(lo), "f"(hi)); return r;
}
__device__ __forceinline__ float2 unpack2(ull v) {
    float2 r; asm("mov.b64 {%0, %1}, %2;" : "=f"(r.x), "=f"(r.y) : "l"(v)); return r;
}
__device__ __forceinline__ ull relu2(ull v) {
    float2 t = unpack2(v);
    return pack2(fmaxf(t.x, 0.f), fmaxf(t.y, 0.f));
}
__device__ __forceinline__ void red_add_v2(float* p, float a, float b) {
    asm volatile("red.global.add.v2.f32 [%0], {%1,%2};" :: "l"(p), "f"(a), "f"(b) : "memory");
}
__device__ __forceinline__ void red_add_f(float* p, float a) {
    asm volatile("red.global.add.f32 [%0], %1;" :: "l"(p), "f"(a) : "memory");
}

// ---------------- device scratch ----------------
__device__ float d_P [NN*128];
__device__ float d_Q [NN*128];
__device__ float d_Ms[NN*128];
__device__ float d_Rg[NG*128];
__device__ float d_agg[NN*128];
__device__ float d_deg[NN];
__device__ float d_gsum[NG*64];
__device__ float d_gcnt[NG];

// ---------------- K0 / K0b ----------------
__global__ void k_zero() {
    int i = blockIdx.x * blockDim.x + threadIdx.x;
    int stride = gridDim.x * blockDim.x;
    for (int idx = i; idx < NN*128; idx += stride) d_agg[idx] = 0.f;
    for (int idx = i; idx < NN;     idx += stride) d_deg[idx] = 0.f;
    for (int idx = i; idx < NG*64;  idx += stride) d_gsum[idx] = 0.f;
    for (int idx = i; idx < NG;     idx += stride) d_gcnt[idx] = 0.f;
}
__global__ void k_count(const int* __restrict__ ei, const int* __restrict__ batch) {
    int i = blockIdx.x * blockDim.x + threadIdx.x;
    if (i < NE) atomicAdd(&d_deg[ei[NE + i]], 1.f);
    if (i < NN) atomicAdd(&d_gcnt[batch[i]], 1.f);
}

// ---------------- K1: precompute P, Q, Msrc (SIMT f32x2, fp32-exact) ----------------
#define PRE_SMEM ((4352 + 3*8192 + 256) * 4)
__global__ void __launch_bounds__(512, 1)
k_pre(const float* __restrict__ x, const float* __restrict__ ew1,
      const float* __restrict__ eb1, const float* __restrict__ n1w1,
      const float* __restrict__ n1b1) {
    extern __shared__ float sm[];
    float* sXT  = sm;
    float* sWa  = sm + 4352;
    float* sWb  = sWa + 8192;
    float* sWm  = sWb + 8192;
    float* sEb1 = sWm + 8192;
    float* sNb1 = sEb1 + 128;
    int tid = threadIdx.x;
    for (int i = tid; i < 8192; i += 512) {
        sWa[i] = ew1[i];
        sWb[i] = ew1[64*128 + i];
        sWm[i] = n1w1[i];
    }
    if (tid < 128) { sEb1[tid] = eb1[tid]; sNb1[tid] = n1b1[tid]; }
    int n0 = blockIdx.x * 64;
    for (int idx = tid; idx < 64*64; idx += 512) {
        int node = idx >> 6, k = idx & 63;
        int n = n0 + node;
        sXT[k*68 + node] = (n < NN) ? x[(size_t)n*64 + k] : 0.f;
    }
    __syncthreads();
    int tx = tid & 31, wid = tid >> 5;
    int ty = wid & 7, fh = wid >> 3;
    int fbase = fh*64 + tx*2;
    for (int which = 0; which < 3; which++) {
        const float* W = (which == 0) ? sWa : (which == 1) ? sWb : sWm;
        ull acc[4][2];
        #pragma unroll
        for (int p = 0; p < 4; p++)
            #pragma unroll
            for (int j = 0; j < 2; j++) {
                float b = (which == 0) ? sEb1[fbase + j] : (which == 2) ? sNb1[fbase + j] : 0.f;
                acc[p][j] = pack2(b, b);
            }
        #pragma unroll 4
        for (int k = 0; k < 64; k++) {
            float2 B = *(const float2*)&W[k*128 + fbase];
            ull bb0 = pack2(B.x, B.x), bb1 = pack2(B.y, B.y);
            float4 A0 = *(const float4*)&sXT[k*68 + ty*8];
            float4 A1 = *(const float4*)&sXT[k*68 + ty*8 + 4];
            ull a0 = pack2(A0.x, A0.y), a1 = pack2(A0.z, A0.w);
            ull a2 = pack2(A1.x, A1.y), a3 = pack2(A1.z, A1.w);
            ffma2(acc[0][0], a0, bb0); ffma2(acc[0][1], a0, bb1);
            ffma2(acc[1][0], a1, bb0); ffma2(acc[1][1], a1, bb1);
            ffma2(acc[2][0], a2, bb0); ffma2(acc[2][1], a2, bb1);
            ffma2(acc[3][0], a3, bb0); ffma2(acc[3][1], a3, bb1);
        }
        float* dst = (which == 0) ? d_P : (which == 1) ? d_Q : d_Ms;
        #pragma unroll
        for (int p = 0; p < 4; p++) {
            float2 v0 = unpack2(acc[p][0]), v1 = unpack2(acc[p][1]);
            int n_lo = n0 + ty*8 + 2*p;
            if (n_lo < NN)
                *(float2*)&dst[(size_t)n_lo*128 + fbase] = make_float2(v0.x, v1.x);
            if (n_lo + 1 < NN)
                *(float2*)&dst[(size_t)(n_lo+1)*128 + fbase] = make_float2(v0.y, v1.y);
        }
    }
}

// ---------------- K1b ----------------
__global__ void k_rg(const float* __restrict__ u, const float* __restrict__ ew1) {
    int i = blockIdx.x * blockDim.x + threadIdx.x;
    if (i < NG*128) {
        int g = i >> 7, j = i & 127;
        float acc = 0.f;
        #pragma unroll
        for (int k = 0; k < 16; k++) acc += u[g*16 + k] * ew1[(160 + k)*128 + j];
        d_Rg[i] = acc;
    }
}

// ================= K2a: EdgeModel via tf32 mma.sync — 512 thr, mt=2 =================
#define S2A_SMEM (34240 * 4)
__global__ void __launch_bounds__(512, 1)
k2a(const float* __restrict__ ea, const float* __restrict__ ew1,
    const float* __restrict__ ew2, const float* __restrict__ eb2,
    const int* __restrict__ ei, const int* __restrict__ batch,
    float* __restrict__ outE) {
    extern __shared__ float sm[];
    uint32_t* sW1u = (uint32_t*)sm;              // 16gnt x 4ks x 64
    uint32_t* sW2u = (uint32_t*)(sm + 4096);     // 8gnt x 16ks x 64
    uint32_t* sEA  = (uint32_t*)(sm + 12288);    // [128e][36]
    uint32_t* sH1  = (uint32_t*)(sm + 16896);    // [128e][132]
    float*    sB2  = sm + 33792;                 // 64
    int* sRow = (int*)(sm + 33856);
    int* sCol = sRow + 128;
    int* sGr  = sCol + 128;

    int tid = threadIdx.x, lane = tid & 31, w = tid >> 5;
    int wm = w & 3, wn = w >> 2;                 // wm: 32-edge group, wn: N quarter
    int g = lane >> 2, tig = lane & 3;

    // weight staging (fragment order, tf32)
    for (int i = tid; i < 4096; i += 512) {      // W1c^T: gnt = blk>>2, ks = blk&3
        int blk = i >> 6, j = i & 63;
        int gnt = blk >> 2, ks = blk & 3;
        int l = j >> 1, h = j & 1;
        int n = gnt*8 + (l >> 2);
        int k = ks*8 + (l & 3) + h*4;
        sW1u[i] = f2tf(ew1[(128 + k)*128 + n]);
    }
    for (int i = tid; i < 8192; i += 512) {      // W2^T: gnt = blk>>4, ks = blk&15
        int blk = i >> 6, j = i & 63;
        int gnt = blk >> 4, ks = blk & 15;
        int l = j >> 1, h = j & 1;
        int n = gnt*8 + (l >> 2);
        int k = ks*8 + (l & 3) + h*4;
        sW2u[i] = f2tf(ew2[k*64 + n]);
    }
    if (tid < 64) sB2[tid] = eb2[tid];

    for (int t = blockIdx.x; t < NTILE; t += gridDim.x) {
        __syncthreads();
        int e0 = t * 128;
        if (tid < 128) {
            int r = ei[e0 + tid], c = ei[NE + e0 + tid];
            sRow[tid] = r; sCol[tid] = c; sGr[tid] = batch[r];
        }
        for (int i = tid; i < 1024; i += 512) {  // EA [128][32] tf32, stride 36
            int e = i >> 3, kc = i & 7;
            float4 v = *(const float4*)&ea[(size_t)(e0 + e)*32 + kc*4];
            *(uint4*)&sEA[e*36 + kc*4] = make_uint4(f2tf(v.x), f2tf(v.y), f2tf(v.z), f2tf(v.w));
        }
        __syncthreads();

        int elo[2], ehi[2];
        #pragma unroll
        for (int m = 0; m < 2; m++) { elo[m] = wm*32 + m*16 + g; ehi[m] = elo[m] + 8; }

        // ---- GEMM1: H1 = relu(P+Q+R + EA @ W1c)  (K=32, N=128; mt=2, nt=4) ----
        float acc[2][4][4];
        #pragma unroll
        for (int m = 0; m < 2; m++) {
            int r1 = sRow[elo[m]], cc1 = sCol[elo[m]], g1 = sGr[elo[m]];
            int r2 = sRow[ehi[m]], cc2 = sCol[ehi[m]], g2 = sGr[ehi[m]];
            #pragma unroll
            for (int nt = 0; nt < 4; nt++) {
                int c = wn*32 + nt*8 + tig*2;
                float2 pa = *(const float2*)&d_P [(size_t)r1*128 + c];
                float2 qa = *(const float2*)&d_Q [(size_t)cc1*128 + c];
                float2 ra = *(const float2*)&d_Rg[(size_t)g1*128 + c];
                float2 pb = *(const float2*)&d_P [(size_t)r2*128 + c];
                float2 qb = *(const float2*)&d_Q [(size_t)cc2*128 + c];
                float2 rb = *(const float2*)&d_Rg[(size_t)g2*128 + c];
                acc[m][nt][0] = pa.x + qa.x + ra.x; acc[m][nt][1] = pa.y + qa.y + ra.y;
                acc[m][nt][2] = pb.x + qb.x + rb.x; acc[m][nt][3] = pb.y + qb.y + rb.y;
            }
        }
        #pragma unroll
        for (int ks = 0; ks < 4; ks++) {
            uint32_t a[2][4];
            #pragma unroll
            for (int m = 0; m < 2; m++) {
                a[m][0] = sEA[elo[m]*36 + ks*8 + tig];
                a[m][1] = sEA[ehi[m]*36 + ks*8 + tig];
                a[m][2] = sEA[elo[m]*36 + ks*8 + tig + 4];
                a[m][3] = sEA[ehi[m]*36 + ks*8 + tig + 4];
            }
            #pragma unroll
            for (int nt = 0; nt < 4; nt++) {
                const uint32_t* bp = &sW1u[((wn*4 + nt)*4 + ks)*64 + lane*2];
                uint32_t b0 = bp[0], b1 = bp[1];
                mma8(acc[0][nt], a[0], b0, b1);
                mma8(acc[1][nt], a[1], b0, b1);
            }
        }
        #pragma unroll
        for (int m = 0; m < 2; m++)
            #pragma unroll
            for (int nt = 0; nt < 4; nt++) {
                int c = wn*32 + nt*8 + tig*2;
                *(uint2*)&sH1[elo[m]*132 + c] =
                    make_uint2(f2tf(fmaxf(acc[m][nt][0], 0.f)), f2tf(fmaxf(acc[m][nt][1], 0.f)));
                *(uint2*)&sH1[ehi[m]*132 + c] =
                    make_uint2(f2tf(fmaxf(acc[m][nt][2], 0.f)), f2tf(fmaxf(acc[m][nt][3], 0.f)));
            }
        __syncthreads();

        // ---- GEMM2: EN = H1 @ W2 + b2  (K=128, N=64; mt=2, nt=2) ----
        float acc2[2][2][4];
        #pragma unroll
        for (int m = 0; m < 2; m++)
            #pragma unroll
            for (int nt = 0; nt < 2; nt++) {
                int c = wn*16 + nt*8 + tig*2;
                acc2[m][nt][0] = sB2[c]; acc2[m][nt][1] = sB2[c+1];
                acc2[m][nt][2] = sB2[c]; acc2[m][nt][3] = sB2[c+1];
            }
        #pragma unroll 4
        for (int ks = 0; ks < 16; ks++) {
            uint32_t a[2][4];
            #pragma unroll
            for (int m = 0; m < 2; m++) {
                a[m][0] = sH1[elo[m]*132 + ks*8 + tig];
                a[m][1] = sH1[ehi[m]*132 + ks*8 + tig];
                a[m][2] = sH1[elo[m]*132 + ks*8 + tig + 4];
                a[m][3] = sH1[ehi[m]*132 + ks*8 + tig + 4];
            }
            #pragma unroll
            for (int nt = 0; nt < 2; nt++) {
                const uint32_t* bp = &sW2u[((wn*2 + nt)*16 + ks)*64 + lane*2];
                uint32_t b0 = bp[0], b1 = bp[1];
                mma8(acc2[0][nt], a[0], b0, b1);
                mma8(acc2[1][nt], a[1], b0, b1);
            }
        }
        #pragma unroll
        for (int m = 0; m < 2; m++)
            #pragma unroll
            for (int nt = 0; nt < 2; nt++) {
                int c = wn*16 + nt*8 + tig*2;
                *(float2*)&outE[(size_t)(e0 + elo[m])*64 + c] = make_float2(acc2[m][nt][0], acc2[m][nt][1]);
                *(float2*)&outE[(size_t)(e0 + ehi[m])*64 + c] = make_float2(acc2[m][nt][2], acc2[m][nt][3]);
            }
    }
}

// ================= K2b: message MLP via tf32 mma.sync — 512 thr, mt=2 =================
#define S2B_SMEM (50560 * 4)
__global__ void __launch_bounds__(512, 1)
k2b(const float* __restrict__ n1w1, const float* __restrict__ n1w2,
    const float* __restrict__ n1b2,
    const int* __restrict__ ei, const float* __restrict__ edgeNew) {
    extern __shared__ float sm[];
    uint32_t* sW3u = (uint32_t*)sm;              // 16gnt x 8ks x 64
    uint32_t* sW4u = (uint32_t*)(sm + 8192);     // 16gnt x 16ks x 64
    uint32_t* sEN  = (uint32_t*)(sm + 24576);    // [128e][68]
    uint32_t* sH2  = (uint32_t*)(sm + 33280);    // [128e][132]
    float*    sB4  = sm + 50176;                 // 128
    int* sRow = (int*)(sm + 50304);
    int* sCol = sRow + 128;

    int tid = threadIdx.x, lane = tid & 31, w = tid >> 5;
    int wm = w & 3, wn = w >> 2;
    int g = lane >> 2, tig = lane & 3;

    for (int i = tid; i < 8192; i += 512) {      // W3^T: gnt = blk>>3, ks = blk&7
        int blk = i >> 6, j = i & 63;
        int gnt = blk >> 3, ks = blk & 7;
        int l = j >> 1, h = j & 1;
        int n = gnt*8 + (l >> 2);
        int k = ks*8 + (l & 3) + h*4;
        sW3u[i] = f2tf(n1w1[(64 + k)*128 + n]);
    }
    for (int i = tid; i < 16384; i += 512) {     // W4^T: gnt = blk>>4, ks = blk&15
        int blk = i >> 6, j = i & 63;
        int gnt = blk >> 4, ks = blk & 15;
        int l = j >> 1, h = j & 1;
        int n = gnt*8 + (l >> 2);
        int k = ks*8 + (l & 3) + h*4;
        sW4u[i] = f2tf(n1w2[k*128 + n]);
    }
    if (tid < 128) sB4[tid] = n1b2[tid];

    for (int t = blockIdx.x; t < NTILE; t += gridDim.x) {
        __syncthreads();
        int e0 = t * 128;
        if (tid < 128) {
            sRow[tid] = ei[e0 + tid];
            sCol[tid] = ei[NE + e0 + tid];
        }
        for (int i = tid; i < 2048; i += 512) {  // EN [128][64] tf32, stride 68
            int e = i >> 4, kc = i & 15;
            float4 v = *(const float4*)&edgeNew[(size_t)(e0 + e)*64 + kc*4];
            *(uint4*)&sEN[e*68 + kc*4] = make_uint4(f2tf(v.x), f2tf(v.y), f2tf(v.z), f2tf(v.w));
        }
        __syncthreads();

        int elo[2], ehi[2];
        #pragma unroll
        for (int m = 0; m < 2; m++) { elo[m] = wm*32 + m*16 + g; ehi[m] = elo[m] + 8; }

        // ---- GEMM3: H2 = relu(Ms[row] + EN @ W3)  (K=64, N=128; mt=2, nt=4) ----
        float acc[2][4][4];
        #pragma unroll
        for (int m = 0; m < 2; m++) {
            int r1 = sRow[elo[m]], r2 = sRow[ehi[m]];
            #pragma unroll
            for (int nt = 0; nt < 4; nt++) {
                int c = wn*32 + nt*8 + tig*2;
                float2 ma = *(const float2*)&d_Ms[(size_t)r1*128 + c];
                float2 mb = *(const float2*)&d_Ms[(size_t)r2*128 + c];
                acc[m][nt][0] = ma.x; acc[m][nt][1] = ma.y;
                acc[m][nt][2] = mb.x; acc[m][nt][3] = mb.y;
            }
        }
        #pragma unroll
        for (int ks = 0; ks < 8; ks++) {
            uint32_t a[2][4];
            #pragma unroll
            for (int m = 0; m < 2; m++) {
                a[m][0] = sEN[elo[m]*68 + ks*8 + tig];
                a[m][1] = sEN[ehi[m]*68 + ks*8 + tig];
                a[m][2] = sEN[elo[m]*68 + ks*8 + tig + 4];
                a[m][3] = sEN[ehi[m]*68 + ks*8 + tig + 4];
            }
            #pragma unroll
            for (int nt = 0; nt < 4; nt++) {
                const uint32_t* bp = &sW3u[((wn*4 + nt)*8 + ks)*64 + lane*2];
                uint32_t b0 = bp[0], b1 = bp[1];
                mma8(acc[0][nt], a[0], b0, b1);
                mma8(acc[1][nt], a[1], b0, b1);
            }
        }
        #pragma unroll
        for (int m = 0; m < 2; m++)
            #pragma unroll
            for (int nt = 0; nt < 4; nt++) {
                int c = wn*32 + nt*8 + tig*2;
                *(uint2*)&sH2[elo[m]*132 + c] =
                    make_uint2(f2tf(fmaxf(acc[m][nt][0], 0.f)), f2tf(fmaxf(acc[m][nt][1], 0.f)));
                *(uint2*)&sH2[ehi[m]*132 + c] =
                    make_uint2(f2tf(fmaxf(acc[m][nt][2], 0.f)), f2tf(fmaxf(acc[m][nt][3], 0.f)));
            }
        __syncthreads();

        // ---- GEMM4: m = H2 @ W4 + b4  (K=128, N=128; mt=2, nt=4) → scatter ----
        float acc4[2][4][4];
        #pragma unroll
        for (int m = 0; m < 2; m++)
            #pragma unroll
            for (int nt = 0; nt < 4; nt++) {
                int c = wn*32 + nt*8 + tig*2;
                acc4[m][nt][0] = sB4[c]; acc4[m][nt][1] = sB4[c+1];
                acc4[m][nt][2] = sB4[c]; acc4[m][nt][3] = sB4[c+1];
            }
        #pragma unroll 4
        for (int ks = 0; ks < 16; ks++) {
            uint32_t a[2][4];
            #pragma unroll
            for (int m = 0; m < 2; m++) {
                a[m][0] = sH2[elo[m]*132 + ks*8 + tig];
                a[m][1] = sH2[ehi[m]*132 + ks*8 + tig];
                a[m][2] = sH2[elo[m]*132 + ks*8 + tig + 4];
                a[m][3] = sH2[ehi[m]*132 + ks*8 + tig + 4];
            }
            #pragma unroll
            for (int nt = 0; nt < 4; nt++) {
                const uint32_t* bp = &sW4u[((wn*4 + nt)*16 + ks)*64 + lane*2];
                uint32_t b0 = bp[0], b1 = bp[1];
                mma8(acc4[0][nt], a[0], b0, b1);
                mma8(acc4[1][nt], a[1], b0, b1);
            }
        }
        #pragma unroll
        for (int m = 0; m < 2; m++) {
            int c1 = sCol[elo[m]], c2 = sCol[ehi[m]];
            #pragma unroll
            for (int nt = 0; nt < 4; nt++) {
                int c = wn*32 + nt*8 + tig*2;
                red_add_v2(&d_agg[(size_t)c1*128 + c], acc4[m][nt][0], acc4[m][nt][1]);
                red_add_v2(&d_agg[(size_t)c2*128 + c], acc4[m][nt][2], acc4[m][nt][3]);
            }
        }
    }
}

// ---------------- K3: node MLP2 + pooling (SIMT f32x2, fp32-exact) ----------------
#define NODE_SMEM (49280 * 4)
__global__ void __launch_bounds__(512, 1)
k_node(const float* __restrict__ x, const float* __restrict__ u,
       const float* __restrict__ n2w1, const float* __restrict__ n2b1,
       const float* __restrict__ n2w2, const float* __restrict__ n2b2,
       const int* __restrict__ batch, float* __restrict__ outX) {
    extern __shared__ float sm[];
    float* sW1  = sm;
    float* sW2  = sm + 26624;
    float* sB1  = sm + 34816;
    float* sB2  = sm + 34944;
    float* sInT = sm + 35008;
    float* sInv = sm + 49152;
    int*   sBat = (int*)(sm + 49216);

    int tid = threadIdx.x, tx = tid & 31, wid = tid >> 5;
    int ty = wid & 7, fh = wid >> 3;
    int fbase = fh*64 + tx*2;
    int f2 = fh*32 + tx;

    for (int i = tid; i < 26624; i += 512) sW1[i] = n2w1[i];
    for (int i = tid; i < 8192;  i += 512) sW2[i] = n2w2[i];
    if (tid < 128) sB1[tid] = n2b1[tid];
    if (tid < 64)  sB2[tid] = n2b2[tid];

    int n0 = blockIdx.x * 64;
    if (tid < 64) {
        int n = n0 + tid;
        if (n < NN) { sBat[tid] = batch[n]; sInv[tid] = 1.f / fmaxf(d_deg[n], 1.f); }
        else        { sBat[tid] = 0;        sInv[tid] = 0.f; }
    }
    __syncthreads();
    for (int idx = tid; idx < 64*64; idx += 512) {
        int node = idx >> 6, k = idx & 63; int n = n0 + node;
        sInT[k*68 + node] = (n < NN) ? x[(size_t)n*64 + k] : 0.f;
    }
    for (int idx = tid; idx < 64*128; idx += 512) {
        int node = idx >> 7, k = idx & 127; int n = n0 + node;
        sInT[(64 + k)*68 + node] = (n < NN) ? d_agg[(size_t)n*128 + k] * sInv[node] : 0.f;
    }
    for (int idx = tid; idx < 64*16; idx += 512) {
        int node = idx >> 4, k = idx & 15;
        sInT[(192 + k)*68 + node] = u[sBat[node]*16 + k];
    }
    __syncthreads();

    ull acc[4][2];
    #pragma unroll
    for (int p = 0; p < 4; p++) {
        acc[p][0] = pack2(sB1[fbase],     sB1[fbase]);
        acc[p][1] = pack2(sB1[fbase + 1], sB1[fbase + 1]);
    }
    #pragma unroll 4
    for (int k = 0; k < 208; k++) {
        float2 B = *(const float2*)&sW1[k*128 + fbase];
        ull bb0 = pack2(B.x, B.x), bb1 = pack2(B.y, B.y);
        float4 A0 = *(const float4*)&sInT[k*68 + ty*8];
        float4 A1 = *(const float4*)&sInT[k*68 + ty*8 + 4];
        ull a0 = pack2(A0.x, A0.y), a1 = pack2(A0.z, A0.w);
        ull a2 = pack2(A1.x, A1.y), a3 = pack2(A1.z, A1.w);
        ffma2(acc[0][0], a0, bb0); ffma2(acc[0][1], a0, bb1);
        ffma2(acc[1][0], a1, bb0); ffma2(acc[1][1], a1, bb1);
        ffma2(acc[2][0], a2, bb0); ffma2(acc[2][1], a2, bb1);
        ffma2(acc[3][0], a3, bb0); ffma2(acc[3][1], a3, bb1);
    }
    __syncthreads();
    #pragma unroll
    for (int p = 0; p < 4; p++) {
        *(ull*)&sInT[(fbase + 0)*68 + ty*8 + 2*p] = relu2(acc[p][0]);
        *(ull*)&sInT[(fbase + 1)*68 + ty*8 + 2*p] = relu2(acc[p][1]);
    }
    __syncthreads();

    ull acc2[4];
    {
        float b = sB2[f2];
        #pragma unroll
        for (int p = 0; p < 4; p++) acc2[p] = pack2(b, b);
    }
    #pragma unroll 4
    for (int k = 0; k < 128; k++) {
        float bs = sW2[k*64 + f2];
        ull bb = pack2(bs, bs);
        float4 A0 = *(const float4*)&sInT[k*68 + ty*8];
        float4 A1 = *(const float4*)&sInT[k*68 + ty*8 + 4];
        ffma2(acc2[0], pack2(A0.x, A0.y), bb);
        ffma2(acc2[1], pack2(A0.z, A0.w), bb);
        ffma2(acc2[2], pack2(A1.x, A1.y), bb);
        ffma2(acc2[3], pack2(A1.z, A1.w), bb);
    }
    #pragma unroll
    for (int p = 0; p < 4; p++) {
        float2 v = unpack2(acc2[p]);
        int node = ty*8 + 2*p;
        int n_lo = n0 + node;
        if (n_lo < NN) {
            outX[(size_t)n_lo*64 + f2] = v.x;
            red_add_f(&d_gsum[sBat[node]*64 + f2], v.x);
        }
        if (n_lo + 1 < NN) {
            outX[(size_t)(n_lo+1)*64 + f2] = v.y;
            red_add_f(&d_gsum[sBat[node+1]*64 + f2], v.y);
        }
    }
}

// ---------------- K4: global MLP ----------------
__global__ void k_glob(const float* __restrict__ u,
                       const float* __restrict__ gw1, const float* __restrict__ gb1,
                       const float* __restrict__ gw2, const float* __restrict__ gb2,
                       float* __restrict__ outU) {
    __shared__ float sin[80];
    __shared__ float sh[128];
    int g = blockIdx.x, tid = threadIdx.x;
    if (tid < 16) sin[tid] = u[g*16 + tid];
    if (tid < 64) {
        float c = fmaxf(d_gcnt[g], 1.f);
        sin[16 + tid] = d_gsum[g*64 + tid] / c;
    }
    __syncthreads();
    float acc = gb1[tid];
    #pragma unroll 8
    for (int k = 0; k < 80; k++) acc += sin[k] * gw1[k*128 + tid];
    sh[tid] = fmaxf(acc, 0.f);
    __syncthreads();
    if (tid < 32) {
        float a2 = gb2[tid];
        #pragma unroll 8
        for (int k = 0; k < 128; k++) a2 += sh[k] * gw2[k*32 + tid];
        outU[g*32 + tid] = a2;
    }
}

// ---------------- launch ----------------
extern "C" void kernel_launch(void* const* d_in, const int* in_sizes, int n_in,
                              void* d_out, int out_size) {
    const float* x     = (const float*)d_in[0];
    const float* ea    = (const float*)d_in[1];
    const float* u     = (const float*)d_in[2];
    const float* ew1   = (const float*)d_in[3];
    const float* eb1   = (const float*)d_in[4];
    const float* ew2   = (const float*)d_in[5];
    const float* eb2   = (const float*)d_in[6];
    const float* n1w1  = (const float*)d_in[7];
    const float* n1b1  = (const float*)d_in[8];
    const float* n1w2  = (const float*)d_in[9];
    const float* n1b2  = (const float*)d_in[10];
    const float* n2w1  = (const float*)d_in[11];
    const float* n2b1  = (const float*)d_in[12];
    const float* n2w2  = (const float*)d_in[13];
    const float* n2b2  = (const float*)d_in[14];
    const float* gw1   = (const float*)d_in[15];
    const float* gb1   = (const float*)d_in[16];
    const float* gw2   = (const float*)d_in[17];
    const float* gb2   = (const float*)d_in[18];
    const int*   ei    = (const int*)d_in[19];
    const int*   batch = (const int*)d_in[20];

    float* out  = (float*)d_out;
    float* outX = out;
    float* outE = out + (size_t)NN*64;
    float* outU = out + (size_t)NN*64 + (size_t)NE*64;

    cudaFuncSetAttribute(k_pre,  cudaFuncAttributeMaxDynamicSharedMemorySize, PRE_SMEM);
    cudaFuncSetAttribute(k2a,    cudaFuncAttributeMaxDynamicSharedMemorySize, S2A_SMEM);
    cudaFuncSetAttribute(k2b,    cudaFuncAttributeMaxDynamicSharedMemorySize, S2B_SMEM);
    cudaFuncSetAttribute(k_node, cudaFuncAttributeMaxDynamicSharedMemorySize, NODE_SMEM);

    k_zero<<<256, 256>>>();
    k_pre<<<(NN + 63)/64, 512, PRE_SMEM>>>(x, ew1, eb1, n1w1, n1b1);
    k_rg<<<(NG*128 + 255)/256, 256>>>(u, ew1);
    k2a<<<PGRID, 512, S2A_SMEM>>>(ea, ew1, ew2, eb2, ei, batch, outE);
    k2b<<<PGRID, 512, S2B_SMEM>>>(n1w1, n1w2, n1b2, ei, outE);
    k_count<<<(NE + 255)/256, 256>>>(ei, batch);
    k_node<<<(NN + 63)/64, 512, NODE_SMEM>>>(x, u, n2w1, n2b1, n2w2, n2b2, batch, outX);
    k_glob<<<NG, 128>>>(u, gw1, gb1, gw2, gb2, outU);
}